// round 1
// baseline (speedup 1.0000x reference)
#include <cuda_runtime.h>
#include <math.h>

// Problem constants (fixed by the dataset)
#define T_TOK 8192
#define D_DIM 4096
#define E_EXP 64
#define K_SEL 8

// Tiling
#define BM 32          // tokens per block
#define BN 128         // outputs per block (64 gate | 64 cls)
#define BK 32          // k-chunk
#define NTHREADS 256

__global__ __launch_bounds__(NTHREADS, 2)
void router_kernel(const float* __restrict__ x,
                   const float* __restrict__ Wg,
                   const float* __restrict__ Wc,
                   const float* __restrict__ extra_scale,
                   const float* __restrict__ extra_bias,
                   float* __restrict__ out)
{
    __shared__ float As[BK][BM + 4];   // [k][m], padded lead (36 floats, 16B-aligned rows)
    __shared__ float Bs[BK][BN];       // [k][n]
    __shared__ float Lg[BM][BN];       // logits tile for epilogue

    const int tid  = threadIdx.x;
    const int lane = tid & 31;
    const int wrp  = tid >> 5;
    const int t0   = blockIdx.x * BM;

    // --- GEMM: C[32 tokens][128] = X_tile * [Wg;Wc]^T ------------------
    float acc[4][4];
    #pragma unroll
    for (int i = 0; i < 4; ++i)
        #pragma unroll
        for (int j = 0; j < 4; ++j) acc[i][j] = 0.f;

    // X load mapping: each thread loads one float4 per iter
    const int xm  = tid >> 3;            // 0..31 token row
    const int xk4 = (tid & 7) * 4;       // k offset within chunk

    float4 xreg;
    float4 wreg[4];

    // prologue: stage iter 0
    xreg = *(const float4*)(x + (size_t)(t0 + xm) * D_DIM + xk4);
    #pragma unroll
    for (int j = 0; j < 4; ++j) {
        int idx = j * NTHREADS + tid;
        int n = idx >> 3, k4 = (idx & 7) * 4;
        const float* wrow = (n < E_EXP) ? (Wg + (size_t)n * D_DIM)
                                        : (Wc + (size_t)(n - E_EXP) * D_DIM);
        wreg[j] = *(const float4*)(wrow + k4);
    }

    const int NIT = D_DIM / BK;   // 128
    for (int it = 0; it < NIT; ++it) {
        // commit staged regs to smem
        As[xk4 + 0][xm] = xreg.x;
        As[xk4 + 1][xm] = xreg.y;
        As[xk4 + 2][xm] = xreg.z;
        As[xk4 + 3][xm] = xreg.w;
        #pragma unroll
        for (int j = 0; j < 4; ++j) {
            int idx = j * NTHREADS + tid;
            int n = idx >> 3, k4 = (idx & 7) * 4;
            Bs[k4 + 0][n] = wreg[j].x;
            Bs[k4 + 1][n] = wreg[j].y;
            Bs[k4 + 2][n] = wreg[j].z;
            Bs[k4 + 3][n] = wreg[j].w;
        }
        __syncthreads();

        // prefetch next chunk while computing on current
        if (it + 1 < NIT) {
            const int k0 = (it + 1) * BK;
            xreg = *(const float4*)(x + (size_t)(t0 + xm) * D_DIM + k0 + xk4);
            #pragma unroll
            for (int j = 0; j < 4; ++j) {
                int idx = j * NTHREADS + tid;
                int n = idx >> 3, k4 = (idx & 7) * 4;
                const float* wrow = (n < E_EXP) ? (Wg + (size_t)n * D_DIM)
                                                : (Wc + (size_t)(n - E_EXP) * D_DIM);
                wreg[j] = *(const float4*)(wrow + k0 + k4);
            }
        }

        // compute: thread tile 4(M) x 4(N); a broadcast within warp
        #pragma unroll
        for (int kk = 0; kk < BK; ++kk) {
            float4 a = *(const float4*)&As[kk][wrp * 4];
            float4 b = *(const float4*)&Bs[kk][lane * 4];
            acc[0][0] = fmaf(a.x, b.x, acc[0][0]);
            acc[0][1] = fmaf(a.x, b.y, acc[0][1]);
            acc[0][2] = fmaf(a.x, b.z, acc[0][2]);
            acc[0][3] = fmaf(a.x, b.w, acc[0][3]);
            acc[1][0] = fmaf(a.y, b.x, acc[1][0]);
            acc[1][1] = fmaf(a.y, b.y, acc[1][1]);
            acc[1][2] = fmaf(a.y, b.z, acc[1][2]);
            acc[1][3] = fmaf(a.y, b.w, acc[1][3]);
            acc[2][0] = fmaf(a.z, b.x, acc[2][0]);
            acc[2][1] = fmaf(a.z, b.y, acc[2][1]);
            acc[2][2] = fmaf(a.z, b.z, acc[2][2]);
            acc[2][3] = fmaf(a.z, b.w, acc[2][3]);
            acc[3][0] = fmaf(a.w, b.x, acc[3][0]);
            acc[3][1] = fmaf(a.w, b.y, acc[3][1]);
            acc[3][2] = fmaf(a.w, b.z, acc[3][2]);
            acc[3][3] = fmaf(a.w, b.w, acc[3][3]);
        }
        __syncthreads();
    }

    // stage logits to smem
    #pragma unroll
    for (int i = 0; i < 4; ++i) {
        float4 v = make_float4(acc[i][0], acc[i][1], acc[i][2], acc[i][3]);
        *(float4*)&Lg[wrp * 4 + i][lane * 4] = v;
    }
    __syncthreads();

    // --- Epilogue: silu/abs/softmax/top-8, one warp per 4 tokens -------
    const float sc0 = extra_scale[lane];
    const float sc1 = extra_scale[lane + 32];
    const float bi0 = extra_bias[lane];
    const float bi1 = extra_bias[lane + 32];

    #pragma unroll
    for (int j = 0; j < 4; ++j) {
        const int t  = wrp * 4 + j;
        const int e0 = lane;
        const int e1 = lane + 32;

        float g0 = Lg[t][e0],          c0 = Lg[t][E_EXP + e0];
        float g1 = Lg[t][e1],          c1 = Lg[t][E_EXP + e1];

        // score = |cls * silu(gate)|
        float s0 = fabsf(c0 * (g0 / (1.f + expf(-g0))));
        float s1 = fabsf(c1 * (g1 / (1.f + expf(-g1))));

        // softmax (fp32, max-subtracted like jax)
        float mx = fmaxf(s0, s1);
        #pragma unroll
        for (int o = 16; o; o >>= 1) mx = fmaxf(mx, __shfl_xor_sync(0xffffffffu, mx, o));
        float x0 = expf(s0 - mx), x1 = expf(s1 - mx);
        float sm = x0 + x1;
        #pragma unroll
        for (int o = 16; o; o >>= 1) sm += __shfl_xor_sync(0xffffffffu, sm, o);
        float inv = 1.f / sm;
        float p0 = x0 * inv, p1 = x1 * inv;

        float b0 = p0 + bi0, b1 = p1 + bi1;          // selection key
        float w0 = fmaf(p0, sc0, 1.f), w1 = fmaf(p1, sc1, 1.f);  // returned weights

        // top-8 by b, jax tie-break: lower index first
        #pragma unroll
        for (int r = 0; r < K_SEL; ++r) {
            float bv; int bi_; float bw;
            if (b0 > b1) { bv = b0; bi_ = e0; bw = w0; }
            else         { bv = b1; bi_ = e1; bw = w1; }   // e0<e1 always → tie picks e0? no: tie must pick e0
            if (b0 == b1) { bv = b0; bi_ = e0; bw = w0; }
            #pragma unroll
            for (int o = 16; o; o >>= 1) {
                float ov = __shfl_xor_sync(0xffffffffu, bv, o);
                int   oi = __shfl_xor_sync(0xffffffffu, bi_, o);
                float ow = __shfl_xor_sync(0xffffffffu, bw, o);
                if (ov > bv || (ov == bv && oi < bi_)) { bv = ov; bi_ = oi; bw = ow; }
            }
            if (lane == 0) {
                const size_t tg = (size_t)(t0 + t);
                out[tg * K_SEL + r] = bw;                                // weights block
                out[(size_t)T_TOK * K_SEL + tg * K_SEL + r] = (float)bi_; // indices block
            }
            if (bi_ == e0) b0 = -1e30f;
            if (bi_ == e1) b1 = -1e30f;
        }
    }
}

extern "C" void kernel_launch(void* const* d_in, const int* in_sizes, int n_in,
                              void* d_out, int out_size)
{
    const float* x  = (const float*)d_in[0];
    const float* Wg = (const float*)d_in[1];
    const float* Wc = (const float*)d_in[2];
    const float* sc = (const float*)d_in[3];
    const float* bi = (const float*)d_in[4];
    // d_in[5] = topk (compile-time K_SEL=8 for this problem)
    float* out = (float*)d_out;

    dim3 grid(T_TOK / BM);   // 256 blocks
    dim3 block(NTHREADS);
    router_kernel<<<grid, block>>>(x, Wg, Wc, sc, bi, out);
}